// round 2
// baseline (speedup 1.0000x reference)
#include <cuda_runtime.h>
#include <math.h>

#define NTHREADS 512
#define TP       128      // points per tile
#define HDIM     128
#define FDIM     13
#define PDIM     64
#define NREFS    10
#define SHS      132      // sH row stride in floats (padded)
#define SFS      17       // sF row stride in floats (odd -> conflict-free column reads)
#define LN_EPS   1e-5f
#define PI_F     3.14159265358979323846f
#define NSM      148

typedef unsigned long long u64;

// ---- packed f32x2 helpers (Blackwell FFMA2 path; ptxas never emits these from C++) ----
__device__ __forceinline__ u64 pack2(float x) {
    unsigned u = __float_as_uint(x);
    u64 r; asm("mov.b64 %0, {%1, %1};" : "=l"(r) : "r"(u)); return r;
}
__device__ __forceinline__ void unpack2(u64 v, float& x, float& y) {
    unsigned a, b;
    asm("mov.b64 {%0, %1}, %2;" : "=r"(a), "=r"(b) : "l"(v));
    x = __uint_as_float(a); y = __uint_as_float(b);
}
__device__ __forceinline__ u64 fma2(u64 a, u64 b, u64 c) {
    u64 d; asm("fma.rn.f32x2 %0, %1, %2, %3;" : "=l"(d) : "l"(a), "l"(b), "l"(c)); return d;
}
__device__ __forceinline__ u64 lds_u64(const float* p) {
    return *reinterpret_cast<const u64*>(p);
}

// shared memory layout (float offsets)
#define OFF_W1   0                         // 13*128   = 1664
#define OFF_W2   1664                      // 128*128  = 16384
#define OFF_W3   18048                     // 128*64   = 8192
#define OFF_H    26240                     // 128*132  = 16896
#define OFF_F    43136                     // 128*17   = 2176
#define OFF_B1   45312
#define OFF_G1   45440
#define OFF_T1   45568
#define OFF_B2   45696
#define OFF_G2   45824
#define OFF_T2   45952
#define OFF_B3   46080
#define OFF_CRT  46144
#define OFF_SRT  46160
#define OFF_RP   46176
#define OFF_RS   46192                     // 512
#define OFF_RQ   46704                     // 512
#define SMEM_FLOATS 47216                  // 188,864 bytes

__global__ void __launch_bounds__(NTHREADS, 1)
trunk_kernel(const float* __restrict__ coords,
             const float* __restrict__ ref_theta,
             const float* __restrict__ ref_phi,
             const float* __restrict__ gW1, const float* __restrict__ gb1,
             const float* __restrict__ gg1, const float* __restrict__ gt1,
             const float* __restrict__ gW2, const float* __restrict__ gb2,
             const float* __restrict__ gg2, const float* __restrict__ gt2,
             const float* __restrict__ gW3, const float* __restrict__ gb3,
             float* __restrict__ out, int npts)
{
    extern __shared__ float sm[];
    float* sW1 = sm + OFF_W1;
    float* sW2 = sm + OFF_W2;
    float* sW3 = sm + OFF_W3;
    float* sH  = sm + OFF_H;
    float* sF  = sm + OFF_F;
    float* sB1 = sm + OFF_B1;
    float* sG1 = sm + OFF_G1;
    float* sT1 = sm + OFF_T1;
    float* sB2 = sm + OFF_B2;
    float* sG2 = sm + OFF_G2;
    float* sT2 = sm + OFF_T2;
    float* sB3 = sm + OFF_B3;
    float* sCRT = sm + OFF_CRT;
    float* sSRT = sm + OFF_SRT;
    float* sRP  = sm + OFF_RP;
    float* sRs  = sm + OFF_RS;
    float* sRq  = sm + OFF_RQ;

    const int t = threadIdx.x;

    // ---- stage all weights once per (persistent) block ----
    for (int i = t; i < FDIM*HDIM; i += NTHREADS) sW1[i] = gW1[i];
    for (int i = t; i < HDIM*HDIM; i += NTHREADS) sW2[i] = gW2[i];
    for (int i = t; i < HDIM*PDIM; i += NTHREADS) sW3[i] = gW3[i];
    if (t < HDIM) {
        sB1[t] = gb1[t]; sG1[t] = gg1[t]; sT1[t] = gt1[t];
        sB2[t] = gb2[t]; sG2[t] = gg2[t]; sT2[t] = gt2[t];
    }
    if (t < PDIM) sB3[t] = gb3[t];
    if (t < NREFS) {
        float rt = ref_theta[t];
        sCRT[t] = cosf(rt);
        sSRT[t] = sinf(rt);
        sRP[t]  = ref_phi[t];
    }
    __syncthreads();

    const int ntiles = npts / TP;

    for (int tile = blockIdx.x; tile < ntiles; tile += gridDim.x) {
        const int base = tile * TP;

        // ---------- phase 1a: geometric features -> sF ----------
        if (t < TP) {
            float2 c2 = reinterpret_cast<const float2*>(coords)[base + t];
            float th = c2.x, ph = c2.y;
            float st, ct;
            sincosf(th, &st, &ct);
            float* fr = sF + t * SFS;
            #pragma unroll
            for (int r = 0; r < NREFS; r++) {
                float cd = fmaf(st * sSRT[r], cosf(ph - sRP[r]), ct * sCRT[r]);
                cd = fminf(1.0f, fmaxf(-1.0f, cd));
                fr[r] = acosf(cd) * (1.0f / PI_F);
            }
            fr[10] = th * (1.0f / PI_F);
            fr[11] = ph * (0.5f / PI_F);
            fr[12] = 1.0f;
        }
        __syncthreads();

        // ---------- phase 1b: layer1 (13->128) + LN + ReLU -> sH ----------
        {
            const int q  = t >> 7;      // 0..3 : column quarter
            const int p  = t & 127;     // point within tile
            const int c0 = q * 32;

            float f[FDIM];
            #pragma unroll
            for (int k = 0; k < FDIM; k++) f[k] = sF[p*SFS + k];

            u64 acc[16];
            #pragma unroll
            for (int j = 0; j < 16; j++) acc[j] = lds_u64(sB1 + c0 + 2*j);
            #pragma unroll
            for (int k = 0; k < FDIM; k++) {
                u64 a = pack2(f[k]);
                const float* wr = sW1 + k*HDIM + c0;   // broadcast across warp
                #pragma unroll
                for (int j = 0; j < 16; j++)
                    acc[j] = fma2(a, lds_u64(wr + 2*j), acc[j]);
            }

            float v[32];
            float s = 0.0f, s2 = 0.0f;
            #pragma unroll
            for (int j = 0; j < 16; j++) unpack2(acc[j], v[2*j], v[2*j+1]);
            #pragma unroll
            for (int j = 0; j < 32; j++) { s += v[j]; s2 = fmaf(v[j], v[j], s2); }

            sRs[q*128 + p] = s;
            sRq[q*128 + p] = s2;
            __syncthreads();

            float S  = sRs[p] + sRs[128+p] + sRs[256+p] + sRs[384+p];
            float S2 = sRq[p] + sRq[128+p] + sRq[256+p] + sRq[384+p];
            float mu  = S * (1.0f/HDIM);
            float var = fmaf(-mu, mu, S2 * (1.0f/HDIM));
            float rs  = rsqrtf(var + LN_EPS);

            float* hr = sH + p*SHS + c0;
            #pragma unroll
            for (int j = 0; j < 32; j += 4) {
                float4 o;
                o.x = fmaxf(0.0f, fmaf((v[j+0]-mu)*rs, sG1[c0+j+0], sT1[c0+j+0]));
                o.y = fmaxf(0.0f, fmaf((v[j+1]-mu)*rs, sG1[c0+j+1], sT1[c0+j+1]));
                o.z = fmaxf(0.0f, fmaf((v[j+2]-mu)*rs, sG1[c0+j+2], sT1[c0+j+2]));
                o.w = fmaxf(0.0f, fmaf((v[j+3]-mu)*rs, sG1[c0+j+3], sT1[c0+j+3]));
                *reinterpret_cast<float4*>(hr + j) = o;
            }
        }
        __syncthreads();

        // ---------- phase 2: layer2 (128->128) + LN + ReLU, in place in sH ----------
        {
            const int pg = t >> 4;          // 0..31 : 4-point group
            const int cg = t & 15;          // 0..15 : interleaved column-pair
            const float* h0 = sH + (pg*4)*SHS;

            u64 acc[4][4];
            #pragma unroll
            for (int jp = 0; jp < 4; jp++) {
                u64 b0 = lds_u64(sB2 + 32*jp + 2*cg);
                #pragma unroll
                for (int i = 0; i < 4; i++) acc[i][jp] = b0;
            }

            #pragma unroll 8
            for (int k = 0; k < HDIM; k++) {
                u64 a[4];
                #pragma unroll
                for (int i = 0; i < 4; i++) a[i] = pack2(h0[i*SHS + k]);  // broadcast reads
                const float* wr = sW2 + k*HDIM + 2*cg;
                #pragma unroll
                for (int jp = 0; jp < 4; jp++) {
                    u64 b = lds_u64(wr + 32*jp);                          // conflict-free
                    #pragma unroll
                    for (int i = 0; i < 4; i++)
                        acc[i][jp] = fma2(a[i], b, acc[i][jp]);
                }
            }

            // LN across the 16 lanes holding this point's 128 columns
            float v[4][8], s[4], q2[4];
            #pragma unroll
            for (int i = 0; i < 4; i++) {
                float a = 0.0f, b = 0.0f;
                #pragma unroll
                for (int jp = 0; jp < 4; jp++) {
                    float x0, x1; unpack2(acc[i][jp], x0, x1);
                    v[i][2*jp] = x0; v[i][2*jp+1] = x1;
                    a += x0 + x1;
                    b = fmaf(x0, x0, b); b = fmaf(x1, x1, b);
                }
                #pragma unroll
                for (int m = 1; m < 16; m <<= 1) {
                    a += __shfl_xor_sync(0xffffffffu, a, m);
                    b += __shfl_xor_sync(0xffffffffu, b, m);
                }
                s[i] = a; q2[i] = b;
            }
            __syncthreads();   // all reads of sH complete before overwrite

            #pragma unroll
            for (int i = 0; i < 4; i++) {
                float mu  = s[i] * (1.0f/HDIM);
                float var = fmaf(-mu, mu, q2[i] * (1.0f/HDIM));
                float rs  = rsqrtf(var + LN_EPS);
                float* hw = sH + (pg*4 + i)*SHS + 2*cg;
                #pragma unroll
                for (int jp = 0; jp < 4; jp++) {
                    int c = 32*jp + 2*cg;
                    float2 o;
                    o.x = fmaxf(0.0f, fmaf((v[i][2*jp+0]-mu)*rs, sG2[c+0], sT2[c+0]));
                    o.y = fmaxf(0.0f, fmaf((v[i][2*jp+1]-mu)*rs, sG2[c+1], sT2[c+1]));
                    *reinterpret_cast<float2*>(hw + 32*jp) = o;
                }
            }
        }
        __syncthreads();

        // ---------- phase 3: layer3 (128->64) -> global out ----------
        {
            const int pg = t >> 4;
            const int cg = t & 15;
            const float* h0 = sH + (pg*4)*SHS;

            u64 acc[4][2];
            #pragma unroll
            for (int jp = 0; jp < 2; jp++) {
                u64 b0 = lds_u64(sB3 + 32*jp + 2*cg);
                #pragma unroll
                for (int i = 0; i < 4; i++) acc[i][jp] = b0;
            }

            #pragma unroll 8
            for (int k = 0; k < HDIM; k++) {
                const float* wr = sW3 + k*PDIM + 2*cg;
                u64 b0 = lds_u64(wr);
                u64 b1 = lds_u64(wr + 32);
                #pragma unroll
                for (int i = 0; i < 4; i++) {
                    u64 a = pack2(h0[i*SHS + k]);
                    acc[i][0] = fma2(a, b0, acc[i][0]);
                    acc[i][1] = fma2(a, b1, acc[i][1]);
                }
            }

            float* ob = out + (size_t)(base + pg*4) * PDIM + 2*cg;
            #pragma unroll
            for (int i = 0; i < 4; i++) {
                #pragma unroll
                for (int jp = 0; jp < 2; jp++) {
                    float y0, y1; unpack2(acc[i][jp], y0, y1);
                    float2 o; o.x = y0; o.y = y1;
                    *reinterpret_cast<float2*>(ob + i*PDIM + 32*jp) = o;
                }
            }
        }
        // no trailing sync needed: next tile's first sync (after phase 1a, which
        // touches only sF) separates phase-3 sH reads from phase-1b sH writes.
    }
}

extern "C" void kernel_launch(void* const* d_in, const int* in_sizes, int n_in,
                              void* d_out, int out_size)
{
    const float* coords    = (const float*)d_in[0];
    const float* ref_theta = (const float*)d_in[1];
    const float* ref_phi   = (const float*)d_in[2];
    const float* W1 = (const float*)d_in[3];
    const float* b1 = (const float*)d_in[4];
    const float* g1 = (const float*)d_in[5];
    const float* t1 = (const float*)d_in[6];
    const float* W2 = (const float*)d_in[7];
    const float* b2 = (const float*)d_in[8];
    const float* g2 = (const float*)d_in[9];
    const float* t2 = (const float*)d_in[10];
    const float* W3 = (const float*)d_in[11];
    const float* b3 = (const float*)d_in[12];
    float* out = (float*)d_out;

    const int npts   = in_sizes[0] / 2;
    const int ntiles = npts / TP;
    const int smem_bytes = SMEM_FLOATS * (int)sizeof(float);

    cudaFuncSetAttribute(trunk_kernel,
                         cudaFuncAttributeMaxDynamicSharedMemorySize, smem_bytes);

    int grid = NSM < ntiles ? NSM : ntiles;
    if (grid < 1) grid = 1;

    trunk_kernel<<<grid, NTHREADS, smem_bytes>>>(
        coords, ref_theta, ref_phi,
        W1, b1, g1, t1, W2, b2, g2, t2, W3, b3,
        out, npts);
}

// round 5
// speedup vs baseline: 2.2243x; 2.2243x over previous
#include <cuda_runtime.h>
#include <math.h>

#define NTHREADS 512
#define TP       128
#define HDIM     128
#define PDIM     64
#define NREFS    10
#define LN_EPS   1e-5f
#define PI_F     3.14159265358979323846f
#define NSM      148

typedef unsigned int u32;

// ---- smem layout (float offsets) ----
// Weight strides chosen so stride % 32 == 8 -> B-fragment loads are
// bank-conflict-free (bank = 8*j + g + const, all 32 distinct).
#define W1S 136
#define W2S 136
#define W3S 72
#define OFF_W1 0                         // [16][136]  = 2176
#define OFF_W2 (OFF_W1 + 16*W1S)         // [128][136] = 17408
#define OFF_W3 (OFF_W2 + 128*W2S)        // [128][72]  = 9216
#define OFF_H  (OFF_W3 + 128*W3S)        // [128][128] swizzled = 16384
#define OFF_B1 (OFF_H + 128*128)
#define OFF_G1 (OFF_B1 + 128)
#define OFF_T1 (OFF_G1 + 128)
#define OFF_B2 (OFF_T1 + 128)
#define OFF_G2 (OFF_B2 + 128)
#define OFF_T2 (OFF_G2 + 128)
#define OFF_B3 (OFF_T2 + 128)            // 64
#define OFF_PS (OFF_B3 + 64)             // 256 LN partial sums
#define OFF_PQ (OFF_PS + 256)            // 256 LN partial sumsq
#define OFF_CRT (OFF_PQ + 256)           // 16
#define OFF_SRT (OFF_CRT + 16)           // 16
#define OFF_RP  (OFF_SRT + 16)           // 16
#define SMEM_FLOATS (OFF_RP + 16)        // 46576 floats = 186,304 B

// sH XOR swizzle: bank = (col ^ (4*(row&7))) % 32 -> A-fragment reads and
// paired epilogue stores are conflict-free, no padding needed.
__device__ __forceinline__ int shidx(int row, int col) {
    return OFF_H + row * 128 + (col ^ ((row & 7) << 2));
}

__device__ __forceinline__ u32 f2tf(float f) {
    u32 r; asm("cvt.rna.tf32.f32 %0, %1;" : "=r"(r) : "f"(f)); return r;
}

__device__ __forceinline__ void mma8(float c[4], u32 a0, u32 a1, u32 a2, u32 a3,
                                     u32 b0, u32 b1) {
    asm volatile(
        "mma.sync.aligned.m16n8k8.row.col.f32.tf32.tf32.f32 "
        "{%0,%1,%2,%3}, {%4,%5,%6,%7}, {%8,%9}, {%0,%1,%2,%3};\n"
        : "+f"(c[0]), "+f"(c[1]), "+f"(c[2]), "+f"(c[3])
        : "r"(a0), "r"(a1), "r"(a2), "r"(a3), "r"(b0), "r"(b1));
}

// LN (+bias, gamma/beta) + ReLU + tf32 cvt + store back to swizzled sH.
// ncols always 128 here. Contains 2 __syncthreads (uniform across block).
__device__ __forceinline__ void ln_epilogue(
    float sm[], float (&c)[8][4],
    int boff, int goff, int toff,
    int rA, int rB, int half, int j)
{
    float sA = 0.f, qA = 0.f, sB = 0.f, qB = 0.f;
    #pragma unroll
    for (int n = 0; n < 8; n++) {
        int col = 64*half + 8*n + 2*j;
        float b0 = sm[boff + col], b1 = sm[boff + col + 1];
        c[n][0] += b0; c[n][1] += b1; c[n][2] += b0; c[n][3] += b1;
        sA += c[n][0] + c[n][1];
        qA = fmaf(c[n][0], c[n][0], qA); qA = fmaf(c[n][1], c[n][1], qA);
        sB += c[n][2] + c[n][3];
        qB = fmaf(c[n][2], c[n][2], qB); qB = fmaf(c[n][3], c[n][3], qB);
    }
    #pragma unroll
    for (int m = 1; m < 4; m <<= 1) {
        sA += __shfl_xor_sync(0xffffffffu, sA, m);
        qA += __shfl_xor_sync(0xffffffffu, qA, m);
        sB += __shfl_xor_sync(0xffffffffu, sB, m);
        qB += __shfl_xor_sync(0xffffffffu, qB, m);
    }
    if (j == 0) {
        sm[OFF_PS + rA*2 + half] = sA; sm[OFF_PQ + rA*2 + half] = qA;
        sm[OFF_PS + rB*2 + half] = sB; sm[OFF_PQ + rB*2 + half] = qB;
    }
    __syncthreads();
    float SA = sm[OFF_PS + rA*2] + sm[OFF_PS + rA*2 + 1];
    float QA = sm[OFF_PQ + rA*2] + sm[OFF_PQ + rA*2 + 1];
    float SB = sm[OFF_PS + rB*2] + sm[OFF_PS + rB*2 + 1];
    float QB = sm[OFF_PQ + rB*2] + sm[OFF_PQ + rB*2 + 1];
    float muA = SA * (1.0f/HDIM);
    float rsA = rsqrtf(fmaf(-muA, muA, QA * (1.0f/HDIM)) + LN_EPS);
    float muB = SB * (1.0f/HDIM);
    float rsB = rsqrtf(fmaf(-muB, muB, QB * (1.0f/HDIM)) + LN_EPS);

    #pragma unroll
    for (int n = 0; n < 8; n++) {
        int col = 64*half + 8*n + 2*j;
        float g0 = sm[goff + col], g1 = sm[goff + col + 1];
        float t0 = sm[toff + col], t1 = sm[toff + col + 1];
        float y0 = fmaxf(0.f, fmaf((c[n][0] - muA) * rsA, g0, t0));
        float y1 = fmaxf(0.f, fmaf((c[n][1] - muA) * rsA, g1, t1));
        float y2 = fmaxf(0.f, fmaf((c[n][2] - muB) * rsB, g0, t0));
        float y3 = fmaxf(0.f, fmaf((c[n][3] - muB) * rsB, g1, t1));
        uint2 pA; pA.x = f2tf(y0); pA.y = f2tf(y1);
        uint2 pB; pB.x = f2tf(y2); pB.y = f2tf(y3);
        *reinterpret_cast<uint2*>(&sm[shidx(rA, col)]) = pA;
        *reinterpret_cast<uint2*>(&sm[shidx(rB, col)]) = pB;
    }
    __syncthreads();
}

__global__ void __launch_bounds__(NTHREADS, 1)
trunk_kernel(const float* __restrict__ coords,
             const float* __restrict__ ref_theta,
             const float* __restrict__ ref_phi,
             const float* __restrict__ gW1, const float* __restrict__ gb1,
             const float* __restrict__ gg1, const float* __restrict__ gt1,
             const float* __restrict__ gW2, const float* __restrict__ gb2,
             const float* __restrict__ gg2, const float* __restrict__ gt2,
             const float* __restrict__ gW3, const float* __restrict__ gb3,
             float* __restrict__ out, int npts)
{
    extern __shared__ float sm[];
    const int t = threadIdx.x;

    // ---- stage weights (cvt to tf32), params, refs; zero sH ----
    for (int i = t; i < 16*W1S; i += NTHREADS) {
        int r = i / W1S, cc = i % W1S;
        float v = (r < 13 && cc < 128) ? gW1[r*128 + cc] : 0.0f;
        sm[OFF_W1 + i] = __uint_as_float(f2tf(v));
    }
    for (int i = t; i < 128*W2S; i += NTHREADS) {
        int r = i / W2S, cc = i % W2S;
        float v = (cc < 128) ? gW2[r*128 + cc] : 0.0f;
        sm[OFF_W2 + i] = __uint_as_float(f2tf(v));
    }
    for (int i = t; i < 128*W3S; i += NTHREADS) {
        int r = i / W3S, cc = i % W3S;
        float v = (cc < 64) ? gW3[r*64 + cc] : 0.0f;
        sm[OFF_W3 + i] = __uint_as_float(f2tf(v));
    }
    for (int i = t; i < 128*128; i += NTHREADS) sm[OFF_H + i] = 0.0f;
    if (t < HDIM) {
        sm[OFF_B1 + t] = gb1[t]; sm[OFF_G1 + t] = gg1[t]; sm[OFF_T1 + t] = gt1[t];
        sm[OFF_B2 + t] = gb2[t]; sm[OFF_G2 + t] = gg2[t]; sm[OFF_T2 + t] = gt2[t];
    }
    if (t < PDIM) sm[OFF_B3 + t] = gb3[t];
    if (t < NREFS) {
        float rt = ref_theta[t];
        sm[OFF_CRT + t] = cosf(rt);
        sm[OFF_SRT + t] = sinf(rt);
        sm[OFF_RP + t]  = ref_phi[t];
    }

    const int l = t & 31, g = l >> 2, j = l & 3;
    const int w = t >> 5;
    const int mrow = (w >> 1) << 4;     // warp pair shares 16 rows
    const int half = w & 1;             // N-half
    const int rA = mrow + g, rB = rA + 8;
    const int ntiles = npts / TP;

    __syncthreads();

    for (int tile = blockIdx.x; tile < ntiles; tile += gridDim.x) {
        const int base = tile * TP;

        // ---------- features -> sH cols 0..12 (tf32), 4 threads/point ----------
        {
            const int p = t >> 2, q = t & 3;
            float2 cv = reinterpret_cast<const float2*>(coords)[base + p];
            float th = cv.x, ph = cv.y;
            float st, ct;
            sincosf(th, &st, &ct);
            #pragma unroll
            for (int rr = 0; rr < 3; rr++) {
                int r = q + 4*rr;
                if (r < NREFS) {
                    float cd = fmaf(st * sm[OFF_SRT + r], cosf(ph - sm[OFF_RP + r]),
                                    ct * sm[OFF_CRT + r]);
                    cd = fminf(1.0f, fmaxf(-1.0f, cd));
                    float f = acosf(cd) * (1.0f / PI_F);
                    sm[shidx(p, r)] = __uint_as_float(f2tf(f));
                }
            }
            if (q == 3) {
                sm[shidx(p, 10)] = __uint_as_float(f2tf(th * (1.0f / PI_F)));
                sm[shidx(p, 11)] = __uint_as_float(f2tf(ph * (0.5f / PI_F)));
                sm[shidx(p, 12)] = __uint_as_float(f2tf(1.0f));
            }
        }
        __syncthreads();

        // ---------- layer 1: [128,16(pad)] x [16,128] ----------
        {
            float c[8][4] = {};
            #pragma unroll
            for (int kt = 0; kt < 2; kt++) {
                u32 a0 = __float_as_uint(sm[shidx(rA, kt*8 + j)]);
                u32 a1 = __float_as_uint(sm[shidx(rB, kt*8 + j)]);
                u32 a2 = __float_as_uint(sm[shidx(rA, kt*8 + j + 4)]);
                u32 a3 = __float_as_uint(sm[shidx(rB, kt*8 + j + 4)]);
                #pragma unroll
                for (int n = 0; n < 8; n++) {
                    int bidx = OFF_W1 + (kt*8 + j)*W1S + 64*half + 8*n + g;
                    u32 b0 = __float_as_uint(sm[bidx]);
                    u32 b1 = __float_as_uint(sm[bidx + 4*W1S]);
                    mma8(c[n], a0, a1, a2, a3, b0, b1);
                }
            }
            ln_epilogue(sm, c, OFF_B1, OFF_G1, OFF_T1, rA, rB, half, j);
        }

        // ---------- layer 2: [128,128] x [128,128] ----------
        {
            float c[8][4] = {};
            #pragma unroll
            for (int kt = 0; kt < 16; kt++) {
                u32 a0 = __float_as_uint(sm[shidx(rA, kt*8 + j)]);
                u32 a1 = __float_as_uint(sm[shidx(rB, kt*8 + j)]);
                u32 a2 = __float_as_uint(sm[shidx(rA, kt*8 + j + 4)]);
                u32 a3 = __float_as_uint(sm[shidx(rB, kt*8 + j + 4)]);
                #pragma unroll
                for (int n = 0; n < 8; n++) {
                    int bidx = OFF_W2 + (kt*8 + j)*W2S + 64*half + 8*n + g;
                    u32 b0 = __float_as_uint(sm[bidx]);
                    u32 b1 = __float_as_uint(sm[bidx + 4*W2S]);
                    mma8(c[n], a0, a1, a2, a3, b0, b1);
                }
            }
            ln_epilogue(sm, c, OFF_B2, OFF_G2, OFF_T2, rA, rB, half, j);
        }

        // ---------- layer 3: [128,128] x [128,64] -> gmem ----------
        {
            float c[4][4] = {};
            #pragma unroll
            for (int kt = 0; kt < 16; kt++) {
                u32 a0 = __float_as_uint(sm[shidx(rA, kt*8 + j)]);
                u32 a1 = __float_as_uint(sm[shidx(rB, kt*8 + j)]);
                u32 a2 = __float_as_uint(sm[shidx(rA, kt*8 + j + 4)]);
                u32 a3 = __float_as_uint(sm[shidx(rB, kt*8 + j + 4)]);
                #pragma unroll
                for (int n = 0; n < 4; n++) {
                    int bidx = OFF_W3 + (kt*8 + j)*W3S + 32*half + 8*n + g;
                    u32 b0 = __float_as_uint(sm[bidx]);
                    u32 b1 = __float_as_uint(sm[bidx + 4*W3S]);
                    mma8(c[n], a0, a1, a2, a3, b0, b1);
                }
            }
            #pragma unroll
            for (int n = 0; n < 4; n++) {
                int col = 32*half + 8*n + 2*j;
                float b0 = sm[OFF_B3 + col], b1 = sm[OFF_B3 + col + 1];
                float2 oA; oA.x = c[n][0] + b0; oA.y = c[n][1] + b1;
                float2 oB; oB.x = c[n][2] + b0; oB.y = c[n][3] + b1;
                *reinterpret_cast<float2*>(&out[(size_t)(base + rA)*PDIM + col]) = oA;
                *reinterpret_cast<float2*>(&out[(size_t)(base + rB)*PDIM + col]) = oB;
            }
        }
        __syncthreads();   // layer-3 A reads done before next tile's feature writes
    }
}

extern "C" void kernel_launch(void* const* d_in, const int* in_sizes, int n_in,
                              void* d_out, int out_size)
{
    const float* coords    = (const float*)d_in[0];
    const float* ref_theta = (const float*)d_in[1];
    const float* ref_phi   = (const float*)d_in[2];
    const float* W1 = (const float*)d_in[3];
    const float* b1 = (const float*)d_in[4];
    const float* g1 = (const float*)d_in[5];
    const float* t1 = (const float*)d_in[6];
    const float* W2 = (const float*)d_in[7];
    const float* b2 = (const float*)d_in[8];
    const float* g2 = (const float*)d_in[9];
    const float* t2 = (const float*)d_in[10];
    const float* W3 = (const float*)d_in[11];
    const float* b3 = (const float*)d_in[12];
    float* out = (float*)d_out;

    const int npts   = in_sizes[0] / 2;
    const int ntiles = npts / TP;
    const int smem_bytes = SMEM_FLOATS * (int)sizeof(float);

    cudaFuncSetAttribute(trunk_kernel,
                         cudaFuncAttributeMaxDynamicSharedMemorySize, smem_bytes);

    int grid = NSM < ntiles ? NSM : ntiles;
    if (grid < 1) grid = 1;

    trunk_kernel<<<grid, NTHREADS, smem_bytes>>>(
        coords, ref_theta, ref_phi,
        W1, b1, g1, t1, W2, b2, g2, t2, W3, b3,
        out, npts);
}